// round 3
// baseline (speedup 1.0000x reference)
#include <cuda_runtime.h>
#include <cstdint>

// CenterLoss: loss = (1/B) * sum_b clamp(|x_b|^2 + |c_l|^2 - 2 x_b·c_l, 1e-12, 1e12)
//                    + (C-1)*1e-12
// The reference's full [B,C] distmat is masked by a one-hot on labels, so only
// the true-label column survives; masked-out entries clamp to 1e-12 each.
//
// B=16384, C=1000, D=512. One warp per row. Labels are int32 (JAX default
// x64-disabled downgrades jnp.int64 -> int32). Index clamped defensively.

#define B_ROWS 16384
#define C_CLASSES 1000
#define D_DIM 512
#define WARPS_PER_BLOCK 8
#define THREADS (WARPS_PER_BLOCK * 32)

__device__ double g_accum = 0.0;

__global__ __launch_bounds__(THREADS) void center_loss_rows(
    const float* __restrict__ x,
    const int* __restrict__ labels,
    const float* __restrict__ centers)
{
    __shared__ double block_sum;
    const int warp_in_block = threadIdx.x >> 5;
    const int lane = threadIdx.x & 31;
    const int row = blockIdx.x * WARPS_PER_BLOCK + warp_in_block;

    if (threadIdx.x == 0) block_sum = 0.0;
    __syncthreads();

    if (row < B_ROWS) {
        int lbl = labels[row];
        // defensive clamp: never index outside centers even if dtype surprises us
        lbl = (lbl < 0) ? 0 : ((lbl >= C_CLASSES) ? C_CLASSES - 1 : lbl);

        const float4* __restrict__ xr =
            reinterpret_cast<const float4*>(x + (size_t)row * D_DIM);
        const float4* __restrict__ cr =
            reinterpret_cast<const float4*>(centers + (size_t)lbl * D_DIM);

        float xs = 0.f, cs = 0.f, xc = 0.f;
        // 512 floats / 32 lanes = 16 floats = 4 float4 per lane.
        float4 xv[4], cv[4];
#pragma unroll
        for (int i = 0; i < 4; i++) xv[i] = xr[lane + 32 * i];
#pragma unroll
        for (int i = 0; i < 4; i++) cv[i] = cr[lane + 32 * i];
#pragma unroll
        for (int i = 0; i < 4; i++) {
            xs = fmaf(xv[i].x, xv[i].x, xs);
            xs = fmaf(xv[i].y, xv[i].y, xs);
            xs = fmaf(xv[i].z, xv[i].z, xs);
            xs = fmaf(xv[i].w, xv[i].w, xs);
            cs = fmaf(cv[i].x, cv[i].x, cs);
            cs = fmaf(cv[i].y, cv[i].y, cs);
            cs = fmaf(cv[i].z, cv[i].z, cs);
            cs = fmaf(cv[i].w, cv[i].w, cs);
            xc = fmaf(xv[i].x, cv[i].x, xc);
            xc = fmaf(xv[i].y, cv[i].y, xc);
            xc = fmaf(xv[i].z, cv[i].z, xc);
            xc = fmaf(xv[i].w, cv[i].w, xc);
        }

        // warp reduction
#pragma unroll
        for (int o = 16; o > 0; o >>= 1) {
            xs += __shfl_xor_sync(0xFFFFFFFFu, xs, o);
            cs += __shfl_xor_sync(0xFFFFFFFFu, cs, o);
            xc += __shfl_xor_sync(0xFFFFFFFFu, xc, o);
        }

        if (lane == 0) {
            float d = xs + cs - 2.0f * xc;     // same formula as reference
            d = fminf(fmaxf(d, 1e-12f), 1e12f);
            atomicAdd(&block_sum, (double)d);
        }
    }
    __syncthreads();
    if (threadIdx.x == 0) {
        atomicAdd(&g_accum, block_sum);
    }
}

__global__ void center_loss_finalize(float* __restrict__ out)
{
    // single thread: emit scalar, reset accumulator for the next replay
    double loss = g_accum / (double)B_ROWS
                + (double)(C_CLASSES - 1) * 1e-12;
    out[0] = (float)loss;
    g_accum = 0.0;
}

extern "C" void kernel_launch(void* const* d_in, const int* in_sizes, int n_in,
                              void* d_out, int out_size)
{
    const float* x = (const float*)d_in[0];
    const int* labels = (const int*)d_in[1];
    const float* centers = (const float*)d_in[2];
    float* out = (float*)d_out;

    const int blocks = B_ROWS / WARPS_PER_BLOCK;  // 2048
    center_loss_rows<<<blocks, THREADS>>>(x, labels, centers);
    center_loss_finalize<<<1, 1>>>(out);
}